// round 15
// baseline (speedup 1.0000x reference)
#include <cuda_runtime.h>
#include <cuda_fp16.h>
#include <stdint.h>
#include <math.h>

typedef unsigned int u32;

// Problem constants
#define Bn   256
#define Dd   768
#define Nn_  256
#define Ll   2
#define Hh   8
#define Tt   20
#define HDd  96
#define DFf  3072

#define TOK_ELEMS   (Bn*Nn_*Dd)
#define KV_ELEMS    (Ll*Bn*Hh*Nn_*HDd)
#define KV_LOFF     (Bn*Hh*Nn_*HDd)
#define XD_ELEMS    (Bn*Dd)
#define H1_ELEMS    (Bn*DFf)
#define NSPLIT      8

// hi/lo split weight buffer offsets (halves)
#define WSP_Q    0                         // per l: + l*2*Dd*Dd
#define WSP_O    2359296
#define WSP_W1   4718592                   // per l: + l*2*Dd*DFf
#define WSP_W2   14155776
#define WSP_D1   23592960
#define WSP_TOT  24772608

// ---------------- scratch (device globals; allocation is forbidden) ----------
__device__ __align__(16) __half g_tokh[TOK_ELEMS];
__device__ __align__(16) __half g_Wth[4*Dd*Dd];     // Wk/Wv fp16 [N][K] for KV GEMM
__device__ __align__(16) __half g_Wsp[WSP_TOT];     // scan weights, hi/lo fp16 [2][N][K]
__device__ __align__(16) __half g_K[KV_ELEMS];
__device__ __align__(16) __half g_V[KV_ELEMS];
__device__ __align__(16) float  g_x[XD_ELEMS];
__device__ __align__(16) float  g_x2[XD_ELEMS];
__device__ __align__(16) float  g_xn[XD_ELEMS];
__device__ __align__(16) float  g_attn[XD_ELEMS];
__device__ __align__(16) float  g_part[NSPLIT*XD_ELEMS];   // == 2 x H1 for FFN1 partials
__device__ __align__(16) float  g_part2[NSPLIT*XD_ELEMS];  // FFN2 partials
__device__ float  g_cp[Bn*2];

// ---------------- helpers ----------------------------------------------------
__device__ __forceinline__ void mma_f16(float* c, const u32* a, const u32* b) {
    asm volatile(
        "mma.sync.aligned.m16n8k16.row.col.f32.f16.f16.f32 "
        "{%0,%1,%2,%3}, {%4,%5,%6,%7}, {%8,%9}, {%0,%1,%2,%3};\n"
        : "+f"(c[0]), "+f"(c[1]), "+f"(c[2]), "+f"(c[3])
        : "r"(a[0]), "r"(a[1]), "r"(a[2]), "r"(a[3]), "r"(b[0]), "r"(b[1]));
}

__device__ __forceinline__ void ldsm4(u32* r, u32 saddr) {
    asm volatile("ldmatrix.sync.aligned.m8n8.x4.shared.b16 {%0,%1,%2,%3}, [%4];"
                 : "=r"(r[0]), "=r"(r[1]), "=r"(r[2]), "=r"(r[3]) : "r"(saddr));
}

__device__ __forceinline__ void cp16(void* dst, const void* src) {
    u32 s = (u32)__cvta_generic_to_shared(dst);
    asm volatile("cp.async.ca.shared.global [%0], [%1], 16;\n" :: "r"(s), "l"(src));
}

__device__ __forceinline__ float gelu_exact(float v) {
    return 0.5f * v * (1.0f + erff(v * 0.70710678118654752f));
}

// ---------------- tokens = transpose(feats,(0,2,1)) + pos_enc → fp16 ---------
__global__ void tokens_k(const float* __restrict__ feats, const float* __restrict__ pos,
                         __half* __restrict__ tok) {
    __shared__ float tile[32][33];
    int b = blockIdx.z;
    int n0 = blockIdx.x * 32, d0 = blockIdx.y * 32;
    int tx = threadIdx.x, ty = threadIdx.y;
#pragma unroll
    for (int i = 0; i < 32; i += 8)
        tile[ty + i][tx] = feats[((size_t)b * Dd + (d0 + ty + i)) * Nn_ + n0 + tx];
    __syncthreads();
#pragma unroll
    for (int i = 0; i < 32; i += 8) {
        int n = n0 + ty + i, d = d0 + tx;
        tok[((size_t)b * Nn_ + n) * Dd + d] =
            __float2half_rn(tile[tx][ty + i] + pos[(size_t)n * Dd + d]);
    }
}

// ---------------- transpose Wk/Wv → fp16 [N][K] -------------------------------
__global__ void wtrans_k(const float* __restrict__ Wk, const float* __restrict__ Wv,
                         __half* __restrict__ Wt) {
    __shared__ float t[32][33];
    int z = blockIdx.z;
    const float* src = (z < 2) ? (Wk + (size_t)z * Dd * Dd) : (Wv + (size_t)(z - 2) * Dd * Dd);
    __half* dst = Wt + (size_t)z * Dd * Dd;
    int k0 = blockIdx.x * 32, n0 = blockIdx.y * 32;
    int tx = threadIdx.x, ty = threadIdx.y;
#pragma unroll
    for (int i = 0; i < 32; i += 8)
        t[ty + i][tx] = src[(size_t)(k0 + ty + i) * Dd + n0 + tx];
    __syncthreads();
#pragma unroll
    for (int i = 0; i < 32; i += 8)
        dst[(size_t)(n0 + ty + i) * Dd + k0 + tx] = __float2half_rn(t[tx][ty + i]);
}

// ---------------- transpose + hi/lo split: W [K][N] → hi/lo fp16 [N][K] ------
__global__ void wsplit_k(const float* __restrict__ src, __half* __restrict__ dsthi,
                         int K, int N) {
    __shared__ float t[32][33];
    __half* dstlo = dsthi + (size_t)N * K;
    int k0 = blockIdx.x * 32, n0 = blockIdx.y * 32;
    int tx = threadIdx.x, ty = threadIdx.y;
#pragma unroll
    for (int i = 0; i < 32; i += 8)
        t[ty + i][tx] = src[(size_t)(k0 + ty + i) * N + n0 + tx];
    __syncthreads();
#pragma unroll
    for (int i = 0; i < 32; i += 8) {
        float v = t[tx][ty + i];
        __half hi = __float2half_rn(v);
        __half lo = __float2half_rn(v - __half2float(hi));
        size_t off = (size_t)(n0 + ty + i) * K + k0 + tx;
        dsthi[off] = hi;
        dstlo[off] = lo;
    }
}

// ---------------- context init + cp init ------------------------------------
__global__ void context_k(const float* __restrict__ past, const float* __restrict__ w_qinit,
                          const float* __restrict__ b_qinit, const int* __restrict__ intent,
                          float* __restrict__ x, float* __restrict__ cp) {
    int b = blockIdx.x, tid = threadIdx.x;
    __shared__ float pf[96];
    if (tid < 96) pf[tid] = past[b * 96 + tid];
    __syncthreads();
    int it = intent[b] - 1;
    if (it < 0) it = 0;
    if (it > 2) it = 2;
    for (int e = tid; e < Dd; e += 256) {
        float v = w_qinit[it * Dd + e] + b_qinit[e];
#pragma unroll 8
        for (int j = 0; j < 96; j++) v += pf[j] * w_qinit[(3 + j) * Dd + e];
        x[(size_t)b * Dd + e] = v;
    }
    if (tid < 2) cp[b * 2 + tid] = past[b * 96 + 90 + tid];
}

// ---------------- fp16 KV GEMM: 128x128x32, 4 warps, warp tile 64x64 ---------
// Single launch covers all 4 projections: blockIdx.z -> (proj, layer).
__global__ __launch_bounds__(128, 2) void hgemm_kv_k(
    const __half* __restrict__ A, const __half* __restrict__ Wt,
    const float* __restrict__ bk, const float* __restrict__ bv,
    __half* __restrict__ Kb, __half* __restrict__ Vb, int K) {
    constexpr int LDS = 40;
    constexpr int ABUF = 128 * LDS;   // 5120 halves
    extern __shared__ __half smh[];
    int zz = blockIdx.z, proj = zz & 1, l = zz >> 1;
    const __half* Bt = Wt + (size_t)(proj * 2 + l) * Dd * Dd;
    const float* bias = (proj ? bv : bk) + l * Dd;
    __half* C = (proj ? Vb : Kb) + (size_t)l * KV_LOFF;

    int tid = threadIdx.x, warp = tid >> 5, lane = tid & 31;
    int gid = lane >> 2, tg = lane & 3;
    int wm = warp >> 1, wn = warp & 1;
    int m0 = blockIdx.y * 128, n0 = blockIdx.x * 128;

    float c[4][8][4];
#pragma unroll
    for (int i = 0; i < 4; i++)
#pragma unroll
        for (int j = 0; j < 8; j++)
#pragma unroll
            for (int r = 0; r < 4; r++) c[i][j][r] = 0.f;

    auto stage = [&](int kt, int buf) {
        int kpos = kt * 32;
        __half* Ad = smh + buf * ABUF;
        __half* Bd = smh + 3 * ABUF + buf * ABUF;
#pragma unroll
        for (int i = 0; i < 4; i++) {
            int id = tid + i * 128;
            int r = id >> 2, ch = (id & 3) * 8;
            cp16(Ad + r * LDS + ch, A + (size_t)(m0 + r) * K + kpos + ch);
        }
#pragma unroll
        for (int i = 0; i < 4; i++) {
            int id = tid + i * 128;
            int r = id >> 2, ch = (id & 3) * 8;
            cp16(Bd + r * LDS + ch, Bt + (size_t)(n0 + r) * K + kpos + ch);
        }
        asm volatile("cp.async.commit_group;\n");
    };

    int nt = K / 32;
    stage(0, 0);
    if (nt > 1) stage(1, 1);
    int l15 = lane & 15;
    int kh = (lane >> 4) << 3;
    for (int kt = 0; kt < nt; kt++) {
        if (kt + 1 < nt) { asm volatile("cp.async.wait_group 1;\n"); }
        else             { asm volatile("cp.async.wait_group 0;\n"); }
        __syncthreads();
        if (kt + 2 < nt) stage(kt + 2, (kt + 2) % 3);
        const __half* Ac = smh + (kt % 3) * ABUF;
        const __half* Bc = smh + 3 * ABUF + (kt % 3) * ABUF;
        u32 abase = (u32)__cvta_generic_to_shared(Ac);
        u32 bbase = (u32)__cvta_generic_to_shared(Bc);
#pragma unroll
        for (int ks = 0; ks < 2; ks++) {
            int k0 = ks * 16;
            u32 af[4][4];
#pragma unroll
            for (int i = 0; i < 4; i++) {
                int mr0 = wm * 64 + i * 16;
                ldsm4(af[i], abase + (u32)(((mr0 + l15) * LDS + k0 + kh) * 2));
            }
            u32 bf[8][2];
#pragma unroll
            for (int jj = 0; jj < 4; jj++) {
                int nb0 = wn * 64 + jj * 16;
                u32 r4[4];
                ldsm4(r4, bbase + (u32)(((nb0 + l15) * LDS + k0 + kh) * 2));
                bf[2 * jj][0] = r4[0];
                bf[2 * jj + 1][0] = r4[1];
                bf[2 * jj][1] = r4[2];
                bf[2 * jj + 1][1] = r4[3];
            }
#pragma unroll
            for (int i = 0; i < 4; i++)
#pragma unroll
                for (int j = 0; j < 8; j++) mma_f16(c[i][j], af[i], bf[j]);
        }
        // single top sync per tile: compute(kt) completes before barrier of kt+1,
        // so stage(kt+3) can never race a reader.
    }

#pragma unroll
    for (int i = 0; i < 4; i++) {
#pragma unroll
        for (int j = 0; j < 8; j++) {
            int m = m0 + wm * 64 + i * 16 + gid;
            int n = n0 + wn * 64 + j * 8 + 2 * tg;
#pragma unroll
            for (int half_ = 0; half_ < 2; half_++) {
                int mr = m + half_ * 8;
                float v0 = c[i][j][half_ * 2] + bias[n];
                float v1 = c[i][j][half_ * 2 + 1] + bias[n + 1];
                int b = mr >> 8, ntok = mr & 255;
                int h = n / HDd, hd = n % HDd;
                size_t off = (((size_t)(b * Hh + h)) * Nn_ + ntok) * HDd + hd;
                *(__half2*)&C[off] = __halves2half2(__float2half_rn(v0), __float2half_rn(v1));
            }
        }
    }
}

// ---------------- fp16 hi/lo scan GEMM (split-K partials out) ----------------
// AMODE 0: A = fp32 [M,K].
// AMODE 1: A = gelu(biasA + P0 + P1)          (FFN1->FFN2 fold)
// AMODE 2: A = Aold + biasA + sum8(P0 planes); blockIdx.x==0 writes A to xout.
template <int AMODE>
__global__ __launch_bounds__(128) void hgemm_sk(
    const float* __restrict__ A, const float* __restrict__ P0,
    const float* __restrict__ P1, const float* __restrict__ biasA,
    const __half* __restrict__ Wsp, float* __restrict__ Cpart,
    float* __restrict__ xout, int M, int K, int Nc, int klen) {
    extern __shared__ __half smsk[];
    __half* AhiS = smsk;                    // 2 x 2560
    __half* AloS = smsk + 2 * 2560;         // 2 x 2560
    __half* BhiS = smsk + 4 * 2560;         // 2 x 5120
    __half* BloS = smsk + 4 * 2560 + 2 * 5120;
    const __half* Wlo = Wsp + (size_t)Nc * K;

    int tid = threadIdx.x, warp = tid >> 5, lane = tid & 31;
    int gid = lane >> 2, tg = lane & 3;
    int m0 = blockIdx.y * 64;
    int n0 = blockIdx.x * 128;
    int kbase = blockIdx.z * klen;

    float c[4][4][4];
#pragma unroll
    for (int i = 0; i < 4; i++)
#pragma unroll
        for (int j = 0; j < 4; j++)
#pragma unroll
            for (int r = 0; r < 4; r++) c[i][j][r] = 0.f;

    float4 areg[4], aregN[4];
    auto ldgA = [&](int kt, float4* ar) {
        int kpos = kbase + kt * 32;
#pragma unroll
        for (int i = 0; i < 4; i++) {
            int id = tid + i * 128;
            int r = id >> 3, c4 = (id & 7) * 4;
            if (AMODE == 0) {
                ar[i] = *(const float4*)(A + (size_t)(m0 + r) * K + kpos + c4);
            } else if (AMODE == 1) {
                float4 p0 = *(const float4*)(P0 + (size_t)(m0 + r) * K + kpos + c4);
                float4 p1 = *(const float4*)(P1 + (size_t)(m0 + r) * K + kpos + c4);
                float4 bb = *(const float4*)(biasA + kpos + c4);
                ar[i].x = gelu_exact(bb.x + p0.x + p1.x);
                ar[i].y = gelu_exact(bb.y + p0.y + p1.y);
                ar[i].z = gelu_exact(bb.z + p0.z + p1.z);
                ar[i].w = gelu_exact(bb.w + p0.w + p1.w);
            } else {  // AMODE 2
                size_t base = (size_t)(m0 + r) * K + kpos + c4;
                float4 s = *(const float4*)(A + base);
                float4 bb = *(const float4*)(biasA + kpos + c4);
                s.x += bb.x; s.y += bb.y; s.z += bb.z; s.w += bb.w;
#pragma unroll
                for (int q = 0; q < NSPLIT; q++) {
                    float4 p = *(const float4*)(P0 + (size_t)q * XD_ELEMS + base);
                    s.x += p.x; s.y += p.y; s.z += p.z; s.w += p.w;
                }
                ar[i] = s;
                if (blockIdx.x == 0) *(float4*)(xout + base) = s;
            }
        }
    };
    auto cvtstoreA = [&](const float4* ar, int buf) {
        __half* Ah = AhiS + buf * 2560;
        __half* Al = AloS + buf * 2560;
#pragma unroll
        for (int i = 0; i < 4; i++) {
            int id = tid + i * 128;
            int r = id >> 3, c4 = (id & 7) * 4;
            __half hx = __float2half_rn(ar[i].x), hy = __float2half_rn(ar[i].y);
            __half hz = __float2half_rn(ar[i].z), hw = __float2half_rn(ar[i].w);
            __half lx = __float2half_rn(ar[i].x - __half2float(hx));
            __half ly = __float2half_rn(ar[i].y - __half2float(hy));
            __half lz = __float2half_rn(ar[i].z - __half2float(hz));
            __half lw = __float2half_rn(ar[i].w - __half2float(hw));
            __half2* ph = (__half2*)(Ah + r * 40 + c4);
            ph[0] = __halves2half2(hx, hy);
            ph[1] = __halves2half2(hz, hw);
            __half2* pl = (__half2*)(Al + r * 40 + c4);
            pl[0] = __halves2half2(lx, ly);
            pl[1] = __halves2half2(lz, lw);
        }
    };
    auto stageB = [&](int kt, int buf) {
        int kpos = kbase + kt * 32;
        __half* Bh = BhiS + buf * 5120;
        __half* Bl = BloS + buf * 5120;
#pragma unroll
        for (int i = 0; i < 4; i++) {
            int id = tid + i * 128;
            int r = id >> 2, ch = (id & 3) * 8;
            cp16(Bh + r * 40 + ch, Wsp + (size_t)(n0 + r) * K + kpos + ch);
            cp16(Bl + r * 40 + ch, Wlo + (size_t)(n0 + r) * K + kpos + ch);
        }
        asm volatile("cp.async.commit_group;\n");
    };

    int nt = klen >> 5;
    ldgA(0, areg);
    stageB(0, 0);
    int l15 = lane & 15;
    int kh = (lane >> 4) << 3;
    for (int kt = 0; kt < nt; kt++) {
        int buf = kt & 1;
        cvtstoreA(areg, buf);
        asm volatile("cp.async.wait_group 0;\n");  // B(kt) arrived
        __syncthreads();                            // A visible; compute(kt-1) done
        if (kt + 1 < nt) {
            ldgA(kt + 1, aregN);
            stageB(kt + 1, (kt + 1) & 1);
        }
        const __half* Ah = AhiS + buf * 2560;
        const __half* Al = AloS + buf * 2560;
        const __half* Bh = BhiS + buf * 5120;
        const __half* Bl = BloS + buf * 5120;
        u32 bah = (u32)__cvta_generic_to_shared(Ah);
        u32 bal = (u32)__cvta_generic_to_shared(Al);
        u32 bbh = (u32)__cvta_generic_to_shared(Bh);
        u32 bbl = (u32)__cvta_generic_to_shared(Bl);
#pragma unroll
        for (int ks = 0; ks < 2; ks++) {
            int k0 = ks * 16;
            u32 afh[4][4], afl[4][4];
#pragma unroll
            for (int i = 0; i < 4; i++) {
                u32 off = (u32)(((i * 16 + l15) * 40 + k0 + kh) * 2);
                ldsm4(afh[i], bah + off);
                ldsm4(afl[i], bal + off);
            }
            u32 bfh[4][2], bfl[4][2];
#pragma unroll
            for (int jj = 0; jj < 2; jj++) {
                int nb0 = warp * 32 + jj * 16;
                u32 off = (u32)(((nb0 + l15) * 40 + k0 + kh) * 2);
                u32 r4[4];
                ldsm4(r4, bbh + off);
                bfh[2 * jj][0] = r4[0]; bfh[2 * jj + 1][0] = r4[1];
                bfh[2 * jj][1] = r4[2]; bfh[2 * jj + 1][1] = r4[3];
                ldsm4(r4, bbl + off);
                bfl[2 * jj][0] = r4[0]; bfl[2 * jj + 1][0] = r4[1];
                bfl[2 * jj][1] = r4[2]; bfl[2 * jj + 1][1] = r4[3];
            }
#pragma unroll
            for (int i = 0; i < 4; i++)
#pragma unroll
                for (int j = 0; j < 4; j++) {
                    mma_f16(c[i][j], afh[i], bfh[j]);
                    mma_f16(c[i][j], afh[i], bfl[j]);
                    mma_f16(c[i][j], afl[i], bfh[j]);
                }
        }
#pragma unroll
        for (int i = 0; i < 4; i++) areg[i] = aregN[i];
        // no bottom sync: buffers alternate; top sync of next iter orders reuse.
    }

#pragma unroll
    for (int i = 0; i < 4; i++) {
#pragma unroll
        for (int j = 0; j < 4; j++) {
            int m = m0 + i * 16 + gid;
            int n = n0 + warp * 32 + j * 8 + 2 * tg;
#pragma unroll
            for (int half_ = 0; half_ < 2; half_++) {
                int mr = m + half_ * 8;
                *(float2*)&Cpart[(size_t)blockIdx.z * M * Nc + (size_t)mr * Nc + n] =
                    make_float2(c[i][j][half_ * 2], c[i][j][half_ * 2 + 1]);
            }
        }
    }
}

// ---------------- fused: x += bias + sum8(part); xn = LN(x)*g + b ------------
__global__ void reduce_res_ln_k(const float* __restrict__ part, const float* __restrict__ bias,
                                float* __restrict__ x, const float* __restrict__ g,
                                const float* __restrict__ bb, float* __restrict__ xn) {
    int b = blockIdx.x, tid = threadIdx.x;
    __shared__ float red[8];
    int lane = tid & 31, w = tid >> 5;
    float v[3];
    float s = 0.f;
#pragma unroll
    for (int r = 0; r < 3; r++) {
        int e = tid + 256 * r;
        int idx = b * Dd + e;
        float p = bias[e];
#pragma unroll
        for (int q = 0; q < NSPLIT; q++) p += part[q * XD_ELEMS + idx];
        v[r] = x[idx] + p;
        x[idx] = v[r];
        s += v[r];
    }
#pragma unroll
    for (int o = 16; o; o >>= 1) s += __shfl_xor_sync(0xffffffffu, s, o);
    if (lane == 0) red[w] = s;
    __syncthreads();
    float mean = (red[0] + red[1] + red[2] + red[3] + red[4] + red[5] + red[6] + red[7]) *
                 (1.0f / 768.0f);
    __syncthreads();
    float vs = 0.f;
#pragma unroll
    for (int r = 0; r < 3; r++) { float d = v[r] - mean; vs += d * d; }
#pragma unroll
    for (int o = 16; o; o >>= 1) vs += __shfl_xor_sync(0xffffffffu, vs, o);
    if (lane == 0) red[w] = vs;
    __syncthreads();
    float var = (red[0] + red[1] + red[2] + red[3] + red[4] + red[5] + red[6] + red[7]) *
                (1.0f / 768.0f);
    float rstd = rsqrtf(var + 1e-5f);
#pragma unroll
    for (int r = 0; r < 3; r++) {
        int e = tid + 256 * r;
        xn[b * Dd + e] = (v[r] - mean) * rstd * g[e] + bb[e];
    }
}

// ---------------- fused pre-step + LN1 (standalone, t=0 only) ----------------
__global__ void prestep_ln_k(float* __restrict__ x, const float* __restrict__ cp,
                             const float* __restrict__ w_pp, const float* __restrict__ b_pp,
                             const float* __restrict__ g_pp, const float* __restrict__ be_pp,
                             const float* __restrict__ te, const float* __restrict__ g1,
                             const float* __restrict__ b1_, float* __restrict__ xn) {
    int b = blockIdx.x, tid = threadIdx.x;
    __shared__ float red[8];
    int lane = tid & 31, w = tid >> 5;
    float c0 = cp[b * 2], c1 = cp[b * 2 + 1];
    float v[3];
    float s = 0.f;
#pragma unroll
    for (int r = 0; r < 3; r++) {
        int e = tid + 256 * r;
        v[r] = c0 * w_pp[e] + c1 * w_pp[Dd + e] + b_pp[e];
        s += v[r];
    }
#pragma unroll
    for (int o = 16; o; o >>= 1) s += __shfl_xor_sync(0xffffffffu, s, o);
    if (lane == 0) red[w] = s;
    __syncthreads();
    float mean = (red[0] + red[1] + red[2] + red[3] + red[4] + red[5] + red[6] + red[7]) *
                 (1.0f / 768.0f);
    __syncthreads();
    float vs = 0.f;
#pragma unroll
    for (int r = 0; r < 3; r++) { float d = v[r] - mean; vs += d * d; }
#pragma unroll
    for (int o = 16; o; o >>= 1) vs += __shfl_xor_sync(0xffffffffu, vs, o);
    if (lane == 0) red[w] = vs;
    __syncthreads();
    float var = (red[0] + red[1] + red[2] + red[3] + red[4] + red[5] + red[6] + red[7]) *
                (1.0f / 768.0f);
    float rstd = rsqrtf(var + 1e-5f);
    float xv[3];
    float s2 = 0.f;
#pragma unroll
    for (int r = 0; r < 3; r++) {
        int e = tid + 256 * r;
        float pq = (v[r] - mean) * rstd * g_pp[e] + be_pp[e];
        pq = fmaxf(pq, 0.f);
        xv[r] = x[b * Dd + e] + pq + te[e];
        x[b * Dd + e] = xv[r];
        s2 += xv[r];
    }
    __syncthreads();
#pragma unroll
    for (int o = 16; o; o >>= 1) s2 += __shfl_xor_sync(0xffffffffu, s2, o);
    if (lane == 0) red[w] = s2;
    __syncthreads();
    float mean2 = (red[0] + red[1] + red[2] + red[3] + red[4] + red[5] + red[6] + red[7]) *
                  (1.0f / 768.0f);
    __syncthreads();
    float vs2 = 0.f;
#pragma unroll
    for (int r = 0; r < 3; r++) { float d = xv[r] - mean2; vs2 += d * d; }
#pragma unroll
    for (int o = 16; o; o >>= 1) vs2 += __shfl_xor_sync(0xffffffffu, vs2, o);
    if (lane == 0) red[w] = vs2;
    __syncthreads();
    float var2 = (red[0] + red[1] + red[2] + red[3] + red[4] + red[5] + red[6] + red[7]) *
                 (1.0f / 768.0f);
    float rstd2 = rsqrtf(var2 + 1e-5f);
#pragma unroll
    for (int r = 0; r < 3; r++) {
        int e = tid + 256 * r;
        xn[b * Dd + e] = (xv[r] - mean2) * rstd2 * g1[e] + b1_[e];
    }
}

// ---------------- attention: 384 threads; 2 rows/warp scores; 8-seg AV -------
__global__ __launch_bounds__(384) void attn_k(const float* __restrict__ part,
                                              const float* __restrict__ bq,
                                              const __half* __restrict__ Kl,
                                              const __half* __restrict__ Vl,
                                              float* __restrict__ out) {
    const float SCALE = 0.1020620726159657f;  // 1/sqrt(96)
    int bh = blockIdx.x;
    int b = bh >> 3, h = bh & 7;
    const __half* Kp = Kl + (size_t)(b * Hh + h) * Nn_ * HDd;
    const __half* Vp = Vl + (size_t)(b * Hh + h) * Nn_ * HDd;
    int tid = threadIdx.x, lane = tid & 31, w = tid >> 5;
    __shared__ float qs[HDd];
    __shared__ float sa[Nn_];
    __shared__ float red[12];
    __shared__ float red2[12];
    __shared__ float2 vpart[8][48];
    if (tid < HDd) {
        int idx = b * Dd + h * HDd + tid;
        float qv = bq[h * HDd + tid];
#pragma unroll
        for (int r = 0; r < NSPLIT; r++) qv += part[r * XD_ELEMS + idx];
        qs[tid] = qv;
    }
    __syncthreads();
    {
        int sub = lane & 15;
        int rhalf = lane >> 4;
        float q0 = qs[sub * 6 + 0], q1 = qs[sub * 6 + 1], q2 = qs[sub * 6 + 2];
        float q3 = qs[sub * 6 + 3], q4 = qs[sub * 6 + 4], q5 = qs[sub * 6 + 5];
        for (int pr = w; pr < 128; pr += 12) {
            int n = 2 * pr + rhalf;
            const __half2* kr = (const __half2*)(Kp + (size_t)n * HDd);
            float2 k0 = __half22float2(kr[sub * 3 + 0]);
            float2 k1 = __half22float2(kr[sub * 3 + 1]);
            float2 k2 = __half22float2(kr[sub * 3 + 2]);
            float p = q0 * k0.x + q1 * k0.y + q2 * k1.x + q3 * k1.y + q4 * k2.x + q5 * k2.y;
#pragma unroll
            for (int o = 8; o; o >>= 1) p += __shfl_xor_sync(0xffffffffu, p, o);
            if (sub == 0) sa[n] = p * SCALE;
        }
    }
    __syncthreads();
    float m = (tid < Nn_) ? sa[tid] : -1e30f;
#pragma unroll
    for (int o = 16; o; o >>= 1) m = fmaxf(m, __shfl_xor_sync(0xffffffffu, m, o));
    if (lane == 0) red[w] = m;
    __syncthreads();
    m = red[0];
#pragma unroll
    for (int i = 1; i < 12; i++) m = fmaxf(m, red[i]);
    float e = 0.f;
    if (tid < Nn_) {
        e = expf(sa[tid] - m);
        sa[tid] = e;
    }
#pragma unroll
    for (int o = 16; o; o >>= 1) e += __shfl_xor_sync(0xffffffffu, e, o);
    if (lane == 0) red2[w] = e;
    __syncthreads();
    float tot = 0.f;
#pragma unroll
    for (int i = 0; i < 12; i++) tot += red2[i];
    float inv = 1.0f / tot;
    int seg = tid / 48, p_ = tid % 48;
    int ns = seg * 32;
    float2 acc = make_float2(0.f, 0.f);
#pragma unroll 8
    for (int n = ns; n < ns + 32; n++) {
        float2 vv = __half22float2(((const __half2*)(Vp + (size_t)n * HDd))[p_]);
        float sv = sa[n];
        acc.x += sv * vv.x;
        acc.y += sv * vv.y;
    }
    vpart[seg][p_] = acc;
    __syncthreads();
    if (tid < 48) {
        float2 r = make_float2(0.f, 0.f);
#pragma unroll
        for (int s2 = 0; s2 < 8; s2++) {
            float2 pv = vpart[s2][tid];
            r.x += pv.x;
            r.y += pv.y;
        }
        out[(size_t)b * Dd + h * HDd + 2 * tid] = r.x * inv;
        out[(size_t)b * Dd + h * HDd + 2 * tid + 1] = r.y * inv;
    }
}

// ---------------- fused decoder tail + next-step prestep ---------------------
__global__ __launch_bounds__(256) void dec2pre_k(
    const float* __restrict__ part, const float* __restrict__ bd1,
    const float* __restrict__ w2, const float* __restrict__ b2,
    float* __restrict__ cp, float* __restrict__ out, int t, int last,
    float* __restrict__ x, const float* __restrict__ w_pp, const float* __restrict__ b_pp,
    const float* __restrict__ g_pp, const float* __restrict__ be_pp,
    const float* __restrict__ te, const float* __restrict__ g1,
    const float* __restrict__ b1_, float* __restrict__ xn) {
    int b = blockIdx.x, tid = threadIdx.x;
    int lane = tid & 31, w = tid >> 5;
    __shared__ float red[8];
    __shared__ float r0s[8], r1s[8];
    __shared__ float cps[2];
    float a0 = 0.f, a1 = 0.f;
#pragma unroll
    for (int r = 0; r < 3; r++) {
        int e = tid + 256 * r;
        int idx = b * Dd + e;
        float s = bd1[e];
#pragma unroll
        for (int q = 0; q < NSPLIT; q++) s += part[q * XD_ELEMS + idx];
        float ge = gelu_exact(s);
        a0 += ge * w2[e * 2];
        a1 += ge * w2[e * 2 + 1];
    }
#pragma unroll
    for (int o = 16; o; o >>= 1) {
        a0 += __shfl_xor_sync(0xffffffffu, a0, o);
        a1 += __shfl_xor_sync(0xffffffffu, a1, o);
    }
    if (lane == 0) { r0s[w] = a0; r1s[w] = a1; }
    __syncthreads();
    if (tid == 0) {
        float d0 = b2[0], d1 = b2[1];
#pragma unroll
        for (int i = 0; i < 8; i++) { d0 += r0s[i]; d1 += r1s[i]; }
        float c0 = cp[b * 2] + d0, c1 = cp[b * 2 + 1] + d1;
        cp[b * 2] = c0;
        cp[b * 2 + 1] = c1;
        out[(size_t)(b * Tt + t) * 2 + 0] = c0;
        out[(size_t)(b * Tt + t) * 2 + 1] = c1;
        cps[0] = c0;
        cps[1] = c1;
    }
    if (last) return;
    __syncthreads();
    float c0 = cps[0], c1 = cps[1];
    float v[3];
    float s = 0.f;
#pragma unroll
    for (int r = 0; r < 3; r++) {
        int e = tid + 256 * r;
        v[r] = c0 * w_pp[e] + c1 * w_pp[Dd + e] + b_pp[e];
        s += v[r];
    }
#pragma unroll
    for (int o = 16; o; o >>= 1) s += __shfl_xor_sync(0xffffffffu, s, o);
    if (lane == 0) red[w] = s;
    __syncthreads();
    float mean = (red[0] + red[1] + red[2] + red[3] + red[4] + red[5] + red[6] + red[7]) *
                 (1.0f / 768.0f);
    __syncthreads();
    float vs = 0.f;
#pragma unroll
    for (int r = 0; r < 3; r++) { float d = v[r] - mean; vs += d * d; }
#pragma unroll
    for (int o = 16; o; o >>= 1) vs += __shfl_xor_sync(0xffffffffu, vs, o);
    if (lane == 0) red[w] = vs;
    __syncthreads();
    float var = (red[0] + red[1] + red[2] + red[3] + red[4] + red[5] + red[6] + red[7]) *
                (1.0f / 768.0f);
    float rstd = rsqrtf(var + 1e-5f);
    float xv[3];
    float s2 = 0.f;
#pragma unroll
    for (int r = 0; r < 3; r++) {
        int e = tid + 256 * r;
        float pq = (v[r] - mean) * rstd * g_pp[e] + be_pp[e];
        pq = fmaxf(pq, 0.f);
        xv[r] = x[b * Dd + e] + pq + te[e];
        x[b * Dd + e] = xv[r];
        s2 += xv[r];
    }
    __syncthreads();
#pragma unroll
    for (int o = 16; o; o >>= 1) s2 += __shfl_xor_sync(0xffffffffu, s2, o);
    if (lane == 0) red[w] = s2;
    __syncthreads();
    float mean2 = (red[0] + red[1] + red[2] + red[3] + red[4] + red[5] + red[6] + red[7]) *
                  (1.0f / 768.0f);
    __syncthreads();
    float vs2 = 0.f;
#pragma unroll
    for (int r = 0; r < 3; r++) { float d = xv[r] - mean2; vs2 += d * d; }
#pragma unroll
    for (int o = 16; o; o >>= 1) vs2 += __shfl_xor_sync(0xffffffffu, vs2, o);
    if (lane == 0) red[w] = vs2;
    __syncthreads();
    float var2 = (red[0] + red[1] + red[2] + red[3] + red[4] + red[5] + red[6] + red[7]) *
                 (1.0f / 768.0f);
    float rstd2 = rsqrtf(var2 + 1e-5f);
#pragma unroll
    for (int r = 0; r < 3; r++) {
        int e = tid + 256 * r;
        xn[b * Dd + e] = (xv[r] - mean2) * rstd2 * g1[e] + b1_[e];
    }
}

// ---------------- host orchestration -----------------------------------------
extern "C" void kernel_launch(void* const* d_in, const int* in_sizes, int n_in,
                              void* d_out, int out_size) {
    const float* feats   = (const float*)d_in[0];
    const float* past    = (const float*)d_in[1];
    const float* w_qinit = (const float*)d_in[2];
    const float* b_qinit = (const float*)d_in[3];
    const float* pos_enc = (const float*)d_in[4];
    const float* w_pp    = (const float*)d_in[5];
    const float* b_pp    = (const float*)d_in[6];
    const float* g_pp    = (const float*)d_in[7];
    const float* be_pp   = (const float*)d_in[8];
    const float* time_emb= (const float*)d_in[9];
    const float* Wq      = (const float*)d_in[10];
    const float* bq      = (const float*)d_in[11];
    const float* Wk      = (const float*)d_in[12];
    const float* bk      = (const float*)d_in[13];
    const float* Wv      = (const float*)d_in[14];
    const float* bv      = (const float*)d_in[15];
    const float* Wo      = (const float*)d_in[16];
    const float* bo      = (const float*)d_in[17];
    const float* ln1_g   = (const float*)d_in[18];
    const float* ln1_b   = (const float*)d_in[19];
    const float* W1      = (const float*)d_in[20];
    const float* b1      = (const float*)d_in[21];
    const float* W2      = (const float*)d_in[22];
    const float* b2      = (const float*)d_in[23];
    const float* ln2_g   = (const float*)d_in[24];
    const float* ln2_b   = (const float*)d_in[25];
    const float* w_dec1  = (const float*)d_in[26];
    const float* b_dec1  = (const float*)d_in[27];
    const float* w_dec2  = (const float*)d_in[28];
    const float* b_dec2  = (const float*)d_in[29];
    const int*   intent  = (const int*)d_in[30];
    float* out = (float*)d_out;

    float *x, *x2, *xn, *att, *part, *part2, *cp;
    __half *tokh, *Wth, *Wsp, *Kb, *Vb;
    cudaGetSymbolAddress((void**)&tokh,  g_tokh);
    cudaGetSymbolAddress((void**)&Wth,   g_Wth);
    cudaGetSymbolAddress((void**)&Wsp,   g_Wsp);
    cudaGetSymbolAddress((void**)&Kb,    g_K);
    cudaGetSymbolAddress((void**)&Vb,    g_V);
    cudaGetSymbolAddress((void**)&x,     g_x);
    cudaGetSymbolAddress((void**)&x2,    g_x2);
    cudaGetSymbolAddress((void**)&xn,    g_xn);
    cudaGetSymbolAddress((void**)&att,   g_attn);
    cudaGetSymbolAddress((void**)&part,  g_part);
    cudaGetSymbolAddress((void**)&part2, g_part2);
    cudaGetSymbolAddress((void**)&cp,    g_cp);

    const int SMH  = 3 * (128 * 40 + 128 * 40) * 2;  // 61440 B, ring-3
    const int SMSK = 61440;                          // hi/lo double-buffer
    cudaFuncSetAttribute(hgemm_kv_k, cudaFuncAttributeMaxDynamicSharedMemorySize, SMH);
    cudaFuncSetAttribute(hgemm_sk<0>, cudaFuncAttributeMaxDynamicSharedMemorySize, SMSK);
    cudaFuncSetAttribute(hgemm_sk<1>, cudaFuncAttributeMaxDynamicSharedMemorySize, SMSK);
    cudaFuncSetAttribute(hgemm_sk<2>, cudaFuncAttributeMaxDynamicSharedMemorySize, SMSK);

    // Phase 1: prep + KV projections (single launch, grid.z = 4)
    tokens_k<<<dim3(Nn_ / 32, Dd / 32, Bn), dim3(32, 8)>>>(feats, pos_enc, tokh);
    wtrans_k<<<dim3(Dd / 32, Dd / 32, 4), dim3(32, 8)>>>(Wk, Wv, Wth);
    for (int l = 0; l < Ll; l++) {
        wsplit_k<<<dim3(24, 24), dim3(32, 8)>>>(Wq + (size_t)l * Dd * Dd,
                                                Wsp + WSP_Q + (size_t)l * 2 * Dd * Dd, Dd, Dd);
        wsplit_k<<<dim3(24, 24), dim3(32, 8)>>>(Wo + (size_t)l * Dd * Dd,
                                                Wsp + WSP_O + (size_t)l * 2 * Dd * Dd, Dd, Dd);
        wsplit_k<<<dim3(24, 96), dim3(32, 8)>>>(W1 + (size_t)l * Dd * DFf,
                                                Wsp + WSP_W1 + (size_t)l * 2 * Dd * DFf, Dd, DFf);
        wsplit_k<<<dim3(96, 24), dim3(32, 8)>>>(W2 + (size_t)l * DFf * Dd,
                                                Wsp + WSP_W2 + (size_t)l * 2 * Dd * DFf, DFf, Dd);
    }
    wsplit_k<<<dim3(24, 24), dim3(32, 8)>>>(w_dec1, Wsp + WSP_D1, Dd, Dd);
    context_k<<<Bn, 256>>>(past, w_qinit, b_qinit, intent, x, cp);
    hgemm_kv_k<<<dim3(6, 512, 4), 128, SMH>>>(tokh, Wth, bk, bv, Kb, Vb, Dd);

    // Phase 2: sequential scan (ping-pong x buffers across steps)
    prestep_ln_k<<<Bn, 256>>>(x, cp, w_pp, b_pp, g_pp, be_pp,
                              time_emb, ln1_g, ln1_b, xn);
    float* xa = x;
    float* xb = x2;
    for (int t = 0; t < Tt; t++) {
        for (int l = 0; l < Ll; l++) {
            // q partials = LN1(x) @ Wq
            hgemm_sk<0><<<dim3(6, 4, 8), 128, SMSK>>>(
                xn, nullptr, nullptr, nullptr,
                Wsp + WSP_Q + (size_t)l * 2 * Dd * Dd, part, nullptr, Bn, Dd, Dd, Dd / 8);
            attn_k<<<Bn * Hh, 384>>>(part, bq + l * Dd, Kb + (size_t)l * KV_LOFF,
                                     Vb + (size_t)l * KV_LOFF, att);
            // o partials = attn @ Wo ; x += o + bo ; xn = LN2(x)
            hgemm_sk<0><<<dim3(6, 4, 8), 128, SMSK>>>(
                att, nullptr, nullptr, nullptr,
                Wsp + WSP_O + (size_t)l * 2 * Dd * Dd, part, nullptr, Bn, Dd, Dd, Dd / 8);
            reduce_res_ln_k<<<Bn, 256>>>(part, bo + l * Dd, xa, ln2_g + l * Dd,
                                         ln2_b + l * Dd, xn);
            // FFN1 partials = xn @ W1 (split-K 2; gelu+bias folded into FFN2 stage)
            hgemm_sk<0><<<dim3(24, 4, 2), 128, SMSK>>>(
                xn, nullptr, nullptr, nullptr,
                Wsp + WSP_W1 + (size_t)l * 2 * Dd * DFf, part, nullptr, Bn, Dd, DFf, Dd / 2);
            // FFN2 partials = gelu(b1 + P0 + P1) @ W2  (split-K 8)
            hgemm_sk<1><<<dim3(6, 4, 8), 128, SMSK>>>(
                nullptr, part, part + H1_ELEMS, b1 + (size_t)l * DFf,
                Wsp + WSP_W2 + (size_t)l * 2 * Dd * DFf, part2, nullptr, Bn, DFf, Dd, DFf / 8);
            if (l == 0)
                reduce_res_ln_k<<<Bn, 256>>>(part2, b2 + l * Dd, xa, ln1_g + Dd,
                                             ln1_b + Dd, xn);
        }
        // decoder GEMM with fused l=1 FFN2 reduce: A = xa + b2[1] + sum8(part2),
        // x-update written to xb (blockIdx.x==0 only; xa stays read-only here)
        hgemm_sk<2><<<dim3(6, 4, 8), 128, SMSK>>>(
            xa, part2, nullptr, b2 + Dd, Wsp + WSP_D1, part, xb, Bn, Dd, Dd, Dd / 8);
        int last = (t == Tt - 1);
        const float* te_next = time_emb + (size_t)(last ? t : t + 1) * Dd;
        dec2pre_k<<<Bn, 256>>>(part, b_dec1, w_dec2, b_dec2, cp, out, t, last,
                               xb, w_pp, b_pp, g_pp, be_pp, te_next, ln1_g, ln1_b, xn);
        // swap carry buffers
        float* tmp = xa; xa = xb; xb = tmp;
    }
}

// round 16
// speedup vs baseline: 1.0141x; 1.0141x over previous
#include <cuda_runtime.h>
#include <cuda_fp16.h>
#include <stdint.h>
#include <math.h>

typedef unsigned int u32;

// Problem constants
#define Bn   256
#define Dd   768
#define Nn_  256
#define Ll   2
#define Hh   8
#define Tt   20
#define HDd  96
#define DFf  3072

#define TOK_ELEMS   (Bn*Nn_*Dd)
#define KV_ELEMS    (Ll*Bn*Hh*Nn_*HDd)
#define KV_LOFF     (Bn*Hh*Nn_*HDd)
#define XD_ELEMS    (Bn*Dd)
#define H1_ELEMS    (Bn*DFf)
#define NSPLIT      8

// hi/lo split weight buffer offsets (halves)
#define WSP_Q    0                         // per l: + l*2*Dd*Dd
#define WSP_O    2359296
#define WSP_W1   4718592                   // per l: + l*2*Dd*DFf
#define WSP_W2   14155776
#define WSP_D1   23592960
#define WSP_TOT  24772608

// ---------------- scratch (device globals; allocation is forbidden) ----------
__device__ __align__(16) __half g_tokh[TOK_ELEMS];
__device__ __align__(16) __half g_Wth[4*Dd*Dd];     // Wk/Wv fp16 [N][K] for KV GEMM
__device__ __align__(16) __half g_Wsp[WSP_TOT];     // scan weights, hi/lo fp16 [2][N][K]
__device__ __align__(16) __half g_K[KV_ELEMS];
__device__ __align__(16) __half g_V[KV_ELEMS];
__device__ __align__(16) float  g_x[XD_ELEMS];
__device__ __align__(16) float  g_xn[XD_ELEMS];
__device__ __align__(16) float  g_attn[XD_ELEMS];
__device__ __align__(16) float  g_part[NSPLIT*XD_ELEMS];   // == 2 x H1 for FFN1 partials
__device__ __align__(16) float  g_part2[NSPLIT*XD_ELEMS];  // FFN2 partials
__device__ float  g_cp[Bn*2];

// ---------------- helpers ----------------------------------------------------
__device__ __forceinline__ void mma_f16(float* c, const u32* a, const u32* b) {
    asm volatile(
        "mma.sync.aligned.m16n8k16.row.col.f32.f16.f16.f32 "
        "{%0,%1,%2,%3}, {%4,%5,%6,%7}, {%8,%9}, {%0,%1,%2,%3};\n"
        : "+f"(c[0]), "+f"(c[1]), "+f"(c[2]), "+f"(c[3])
        : "r"(a[0]), "r"(a[1]), "r"(a[2]), "r"(a[3]), "r"(b[0]), "r"(b[1]));
}

__device__ __forceinline__ void ldsm4(u32* r, u32 saddr) {
    asm volatile("ldmatrix.sync.aligned.m8n8.x4.shared.b16 {%0,%1,%2,%3}, [%4];"
                 : "=r"(r[0]), "=r"(r[1]), "=r"(r[2]), "=r"(r[3]) : "r"(saddr));
}

__device__ __forceinline__ void cp16(void* dst, const void* src) {
    u32 s = (u32)__cvta_generic_to_shared(dst);
    asm volatile("cp.async.ca.shared.global [%0], [%1], 16;\n" :: "r"(s), "l"(src));
}

__device__ __forceinline__ float gelu_exact(float v) {
    return 0.5f * v * (1.0f + erff(v * 0.70710678118654752f));
}

// ---------------- tokens = transpose(feats,(0,2,1)) + pos_enc → fp16 ---------
__global__ void tokens_k(const float* __restrict__ feats, const float* __restrict__ pos,
                         __half* __restrict__ tok) {
    __shared__ float tile[32][33];
    int b = blockIdx.z;
    int n0 = blockIdx.x * 32, d0 = blockIdx.y * 32;
    int tx = threadIdx.x, ty = threadIdx.y;
#pragma unroll
    for (int i = 0; i < 32; i += 8)
        tile[ty + i][tx] = feats[((size_t)b * Dd + (d0 + ty + i)) * Nn_ + n0 + tx];
    __syncthreads();
#pragma unroll
    for (int i = 0; i < 32; i += 8) {
        int n = n0 + ty + i, d = d0 + tx;
        tok[((size_t)b * Nn_ + n) * Dd + d] =
            __float2half_rn(tile[tx][ty + i] + pos[(size_t)n * Dd + d]);
    }
}

// ---------------- transpose Wk/Wv → fp16 [N][K] -------------------------------
__global__ void wtrans_k(const float* __restrict__ Wk, const float* __restrict__ Wv,
                         __half* __restrict__ Wt) {
    __shared__ float t[32][33];
    int z = blockIdx.z;
    const float* src = (z < 2) ? (Wk + (size_t)z * Dd * Dd) : (Wv + (size_t)(z - 2) * Dd * Dd);
    __half* dst = Wt + (size_t)z * Dd * Dd;
    int k0 = blockIdx.x * 32, n0 = blockIdx.y * 32;
    int tx = threadIdx.x, ty = threadIdx.y;
#pragma unroll
    for (int i = 0; i < 32; i += 8)
        t[ty + i][tx] = src[(size_t)(k0 + ty + i) * Dd + n0 + tx];
    __syncthreads();
#pragma unroll
    for (int i = 0; i < 32; i += 8)
        dst[(size_t)(n0 + ty + i) * Dd + k0 + tx] = __float2half_rn(t[tx][ty + i]);
}

// ---------------- transpose + hi/lo split: W [K][N] → hi/lo fp16 [N][K] ------
__global__ void wsplit_k(const float* __restrict__ src, __half* __restrict__ dsthi,
                         int K, int N) {
    __shared__ float t[32][33];
    __half* dstlo = dsthi + (size_t)N * K;
    int k0 = blockIdx.x * 32, n0 = blockIdx.y * 32;
    int tx = threadIdx.x, ty = threadIdx.y;
#pragma unroll
    for (int i = 0; i < 32; i += 8)
        t[ty + i][tx] = src[(size_t)(k0 + ty + i) * N + n0 + tx];
    __syncthreads();
#pragma unroll
    for (int i = 0; i < 32; i += 8) {
        float v = t[tx][ty + i];
        __half hi = __float2half_rn(v);
        __half lo = __float2half_rn(v - __half2float(hi));
        size_t off = (size_t)(n0 + ty + i) * K + k0 + tx;
        dsthi[off] = hi;
        dstlo[off] = lo;
    }
}

// ---------------- context init + cp init ------------------------------------
__global__ void context_k(const float* __restrict__ past, const float* __restrict__ w_qinit,
                          const float* __restrict__ b_qinit, const int* __restrict__ intent,
                          float* __restrict__ x, float* __restrict__ cp) {
    int b = blockIdx.x, tid = threadIdx.x;
    __shared__ float pf[96];
    if (tid < 96) pf[tid] = past[b * 96 + tid];
    __syncthreads();
    int it = intent[b] - 1;
    if (it < 0) it = 0;
    if (it > 2) it = 2;
    for (int e = tid; e < Dd; e += 256) {
        float v = w_qinit[it * Dd + e] + b_qinit[e];
#pragma unroll 8
        for (int j = 0; j < 96; j++) v += pf[j] * w_qinit[(3 + j) * Dd + e];
        x[(size_t)b * Dd + e] = v;
    }
    if (tid < 2) cp[b * 2 + tid] = past[b * 96 + 90 + tid];
}

// ---------------- fp16 KV GEMM: 128x128x32, 8 warps, ring-3, 1 sync/tile -----
// Packed launch: blockIdx.z -> (proj, layer). R11-proven tile config.
__global__ __launch_bounds__(256, 2) void hgemm_kv_k(
    const __half* __restrict__ A, const __half* __restrict__ Wt,
    const float* __restrict__ bk, const float* __restrict__ bv,
    __half* __restrict__ Kb, __half* __restrict__ Vb, int K) {
    constexpr int LDS = 40;
    constexpr int ABUF = 128 * LDS;   // 5120 halves
    extern __shared__ __half smh[];
    int zz = blockIdx.z, proj = zz & 1, l = zz >> 1;
    const __half* Bt = Wt + (size_t)(proj * 2 + l) * Dd * Dd;
    const float* bias = (proj ? bv : bk) + l * Dd;
    __half* C = (proj ? Vb : Kb) + (size_t)l * KV_LOFF;

    int tid = threadIdx.x, warp = tid >> 5, lane = tid & 31;
    int gid = lane >> 2, tg = lane & 3;
    int wm = warp >> 2, wn = warp & 3;
    int m0 = blockIdx.y * 128, n0 = blockIdx.x * 128;

    float c[4][4][4];
#pragma unroll
    for (int i = 0; i < 4; i++)
#pragma unroll
        for (int j = 0; j < 4; j++)
#pragma unroll
            for (int r = 0; r < 4; r++) c[i][j][r] = 0.f;

    auto stage = [&](int kt, int buf) {
        int kpos = kt * 32;
        __half* Ad = smh + buf * ABUF;
        __half* Bd = smh + 3 * ABUF + buf * ABUF;
#pragma unroll
        for (int i = 0; i < 2; i++) {
            int id = tid + i * 256;
            int r = id >> 2, ch = (id & 3) * 8;
            cp16(Ad + r * LDS + ch, A + (size_t)(m0 + r) * K + kpos + ch);
        }
#pragma unroll
        for (int i = 0; i < 2; i++) {
            int id = tid + i * 256;
            int r = id >> 2, ch = (id & 3) * 8;
            cp16(Bd + r * LDS + ch, Bt + (size_t)(n0 + r) * K + kpos + ch);
        }
        asm volatile("cp.async.commit_group;\n");
    };

    int nt = K / 32;
    stage(0, 0);
    if (nt > 1) stage(1, 1);
    int l15 = lane & 15;
    int kh = (lane >> 4) << 3;
    for (int kt = 0; kt < nt; kt++) {
        if (kt + 1 < nt) { asm volatile("cp.async.wait_group 1;\n"); }
        else             { asm volatile("cp.async.wait_group 0;\n"); }
        __syncthreads();
        if (kt + 2 < nt) stage(kt + 2, (kt + 2) % 3);
        const __half* Ac = smh + (kt % 3) * ABUF;
        const __half* Bc = smh + 3 * ABUF + (kt % 3) * ABUF;
        u32 abase = (u32)__cvta_generic_to_shared(Ac);
        u32 bbase = (u32)__cvta_generic_to_shared(Bc);
#pragma unroll
        for (int ks = 0; ks < 2; ks++) {
            int k0 = ks * 16;
            u32 af[4][4];
#pragma unroll
            for (int i = 0; i < 4; i++) {
                int mr0 = wm * 64 + i * 16;
                ldsm4(af[i], abase + (u32)(((mr0 + l15) * LDS + k0 + kh) * 2));
            }
            u32 bf[4][2];
#pragma unroll
            for (int jj = 0; jj < 2; jj++) {
                int nb0 = wn * 32 + jj * 16;
                u32 r4[4];
                ldsm4(r4, bbase + (u32)(((nb0 + l15) * LDS + k0 + kh) * 2));
                bf[2 * jj][0] = r4[0];
                bf[2 * jj + 1][0] = r4[1];
                bf[2 * jj][1] = r4[2];
                bf[2 * jj + 1][1] = r4[3];
            }
#pragma unroll
            for (int i = 0; i < 4; i++)
#pragma unroll
                for (int j = 0; j < 4; j++) mma_f16(c[i][j], af[i], bf[j]);
        }
        // single top sync per tile: compute(kt) completes before barrier of kt+1,
        // so stage(kt+3) can never race a reader.
    }

#pragma unroll
    for (int i = 0; i < 4; i++) {
#pragma unroll
        for (int j = 0; j < 4; j++) {
            int m = m0 + wm * 64 + i * 16 + gid;
            int n = n0 + wn * 32 + j * 8 + 2 * tg;
#pragma unroll
            for (int half_ = 0; half_ < 2; half_++) {
                int mr = m + half_ * 8;
                float v0 = c[i][j][half_ * 2] + bias[n];
                float v1 = c[i][j][half_ * 2 + 1] + bias[n + 1];
                int b = mr >> 8, ntok = mr & 255;
                int h = n / HDd, hd = n % HDd;
                size_t off = (((size_t)(b * Hh + h)) * Nn_ + ntok) * HDd + hd;
                *(__half2*)&C[off] = __halves2half2(__float2half_rn(v0), __float2half_rn(v1));
            }
        }
    }
}

// ---------------- fp16 hi/lo scan GEMM (split-K partials out) ----------------
// A fp32 [M,K] (AMODE 0) or gelu(biasA + P0 + P1) (AMODE 1).
// Wsp: hi plane [Nc][K] fp16, lo plane at Wsp + Nc*K.
template <int AMODE>
__global__ __launch_bounds__(128) void hgemm_sk(
    const float* __restrict__ A, const float* __restrict__ P0,
    const float* __restrict__ P1, const float* __restrict__ biasA,
    const __half* __restrict__ Wsp, float* __restrict__ Cpart,
    int M, int K, int Nc, int klen) {
    extern __shared__ __half smsk[];
    __half* AhiS = smsk;                    // 2 x 2560
    __half* AloS = smsk + 2 * 2560;         // 2 x 2560
    __half* BhiS = smsk + 4 * 2560;         // 2 x 5120
    __half* BloS = smsk + 4 * 2560 + 2 * 5120;
    const __half* Wlo = Wsp + (size_t)Nc * K;

    int tid = threadIdx.x, warp = tid >> 5, lane = tid & 31;
    int gid = lane >> 2, tg = lane & 3;
    int m0 = blockIdx.y * 64;
    int n0 = blockIdx.x * 128;
    int kbase = blockIdx.z * klen;

    float c[4][4][4];
#pragma unroll
    for (int i = 0; i < 4; i++)
#pragma unroll
        for (int j = 0; j < 4; j++)
#pragma unroll
            for (int r = 0; r < 4; r++) c[i][j][r] = 0.f;

    float4 areg[4], aregN[4];
    auto ldgA = [&](int kt, float4* ar) {
        int kpos = kbase + kt * 32;
#pragma unroll
        for (int i = 0; i < 4; i++) {
            int id = tid + i * 128;
            int r = id >> 3, c4 = (id & 7) * 4;
            if (AMODE == 0) {
                ar[i] = *(const float4*)(A + (size_t)(m0 + r) * K + kpos + c4);
            } else {
                float4 p0 = *(const float4*)(P0 + (size_t)(m0 + r) * K + kpos + c4);
                float4 p1 = *(const float4*)(P1 + (size_t)(m0 + r) * K + kpos + c4);
                float4 bb = *(const float4*)(biasA + kpos + c4);
                ar[i].x = gelu_exact(bb.x + p0.x + p1.x);
                ar[i].y = gelu_exact(bb.y + p0.y + p1.y);
                ar[i].z = gelu_exact(bb.z + p0.z + p1.z);
                ar[i].w = gelu_exact(bb.w + p0.w + p1.w);
            }
        }
    };
    auto cvtstoreA = [&](const float4* ar, int buf) {
        __half* Ah = AhiS + buf * 2560;
        __half* Al = AloS + buf * 2560;
#pragma unroll
        for (int i = 0; i < 4; i++) {
            int id = tid + i * 128;
            int r = id >> 3, c4 = (id & 7) * 4;
            __half hx = __float2half_rn(ar[i].x), hy = __float2half_rn(ar[i].y);
            __half hz = __float2half_rn(ar[i].z), hw = __float2half_rn(ar[i].w);
            __half lx = __float2half_rn(ar[i].x - __half2float(hx));
            __half ly = __float2half_rn(ar[i].y - __half2float(hy));
            __half lz = __float2half_rn(ar[i].z - __half2float(hz));
            __half lw = __float2half_rn(ar[i].w - __half2float(hw));
            __half2* ph = (__half2*)(Ah + r * 40 + c4);
            ph[0] = __halves2half2(hx, hy);
            ph[1] = __halves2half2(hz, hw);
            __half2* pl = (__half2*)(Al + r * 40 + c4);
            pl[0] = __halves2half2(lx, ly);
            pl[1] = __halves2half2(lz, lw);
        }
    };
    auto stageB = [&](int kt, int buf) {
        int kpos = kbase + kt * 32;
        __half* Bh = BhiS + buf * 5120;
        __half* Bl = BloS + buf * 5120;
#pragma unroll
        for (int i = 0; i < 4; i++) {
            int id = tid + i * 128;
            int r = id >> 2, ch = (id & 3) * 8;
            cp16(Bh + r * 40 + ch, Wsp + (size_t)(n0 + r) * K + kpos + ch);
            cp16(Bl + r * 40 + ch, Wlo + (size_t)(n0 + r) * K + kpos + ch);
        }
        asm volatile("cp.async.commit_group;\n");
    };

    int nt = klen >> 5;
    ldgA(0, areg);
    stageB(0, 0);
    int l15 = lane & 15;
    int kh = (lane >> 4) << 3;
    for (int kt = 0; kt < nt; kt++) {
        int buf = kt & 1;
        cvtstoreA(areg, buf);
        asm volatile("cp.async.wait_group 0;\n");  // B(kt) arrived
        __syncthreads();                            // A visible; compute(kt-1) done
        if (kt + 1 < nt) {
            ldgA(kt + 1, aregN);
            stageB(kt + 1, (kt + 1) & 1);
        }
        const __half* Ah = AhiS + buf * 2560;
        const __half* Al = AloS + buf * 2560;
        const __half* Bh = BhiS + buf * 5120;
        const __half* Bl = BloS + buf * 5120;
        u32 bah = (u32)__cvta_generic_to_shared(Ah);
        u32 bal = (u32)__cvta_generic_to_shared(Al);
        u32 bbh = (u32)__cvta_generic_to_shared(Bh);
        u32 bbl = (u32)__cvta_generic_to_shared(Bl);
#pragma unroll
        for (int ks = 0; ks < 2; ks++) {
            int k0 = ks * 16;
            u32 afh[4][4], afl[4][4];
#pragma unroll
            for (int i = 0; i < 4; i++) {
                u32 off = (u32)(((i * 16 + l15) * 40 + k0 + kh) * 2);
                ldsm4(afh[i], bah + off);
                ldsm4(afl[i], bal + off);
            }
            u32 bfh[4][2], bfl[4][2];
#pragma unroll
            for (int jj = 0; jj < 2; jj++) {
                int nb0 = warp * 32 + jj * 16;
                u32 off = (u32)(((nb0 + l15) * 40 + k0 + kh) * 2);
                u32 r4[4];
                ldsm4(r4, bbh + off);
                bfh[2 * jj][0] = r4[0]; bfh[2 * jj + 1][0] = r4[1];
                bfh[2 * jj][1] = r4[2]; bfh[2 * jj + 1][1] = r4[3];
                ldsm4(r4, bbl + off);
                bfl[2 * jj][0] = r4[0]; bfl[2 * jj + 1][0] = r4[1];
                bfl[2 * jj][1] = r4[2]; bfl[2 * jj + 1][1] = r4[3];
            }
#pragma unroll
            for (int i = 0; i < 4; i++)
#pragma unroll
                for (int j = 0; j < 4; j++) {
                    mma_f16(c[i][j], afh[i], bfh[j]);
                    mma_f16(c[i][j], afh[i], bfl[j]);
                    mma_f16(c[i][j], afl[i], bfh[j]);
                }
        }
#pragma unroll
        for (int i = 0; i < 4; i++) areg[i] = aregN[i];
        // no bottom sync: buffers alternate; top sync of next iter orders reuse.
    }

#pragma unroll
    for (int i = 0; i < 4; i++) {
#pragma unroll
        for (int j = 0; j < 4; j++) {
            int m = m0 + i * 16 + gid;
            int n = n0 + warp * 32 + j * 8 + 2 * tg;
#pragma unroll
            for (int half_ = 0; half_ < 2; half_++) {
                int mr = m + half_ * 8;
                *(float2*)&Cpart[(size_t)blockIdx.z * M * Nc + (size_t)mr * Nc + n] =
                    make_float2(c[i][j][half_ * 2], c[i][j][half_ * 2 + 1]);
            }
        }
    }
}

// ---------------- split-K reduce (S=8) + bias + residual, float4 -------------
__global__ void reduce8res_k(const float* __restrict__ part, const float* __restrict__ bias,
                             float* __restrict__ C) {
    int i4 = (blockIdx.x * 256 + threadIdx.x) * 4;
    int n = i4 % Dd;
    float4 s = *(const float4*)(bias + n);
#pragma unroll
    for (int r = 0; r < NSPLIT; r++) {
        float4 p = *(const float4*)(part + (size_t)r * XD_ELEMS + i4);
        s.x += p.x; s.y += p.y; s.z += p.z; s.w += p.w;
    }
    float4 cv = *(const float4*)(C + i4);
    cv.x += s.x; cv.y += s.y; cv.z += s.z; cv.w += s.w;
    *(float4*)(C + i4) = cv;
}

// ---------------- fused: x += bias + sum8(part); xn = LN(x)*g + b ------------
__global__ void reduce_res_ln_k(const float* __restrict__ part, const float* __restrict__ bias,
                                float* __restrict__ x, const float* __restrict__ g,
                                const float* __restrict__ bb, float* __restrict__ xn) {
    int b = blockIdx.x, tid = threadIdx.x;
    __shared__ float red[8];
    int lane = tid & 31, w = tid >> 5;
    float v[3];
    float s = 0.f;
#pragma unroll
    for (int r = 0; r < 3; r++) {
        int e = tid + 256 * r;
        int idx = b * Dd + e;
        float p = bias[e];
#pragma unroll
        for (int q = 0; q < NSPLIT; q++) p += part[q * XD_ELEMS + idx];
        v[r] = x[idx] + p;
        x[idx] = v[r];
        s += v[r];
    }
#pragma unroll
    for (int o = 16; o; o >>= 1) s += __shfl_xor_sync(0xffffffffu, s, o);
    if (lane == 0) red[w] = s;
    __syncthreads();
    float mean = (red[0] + red[1] + red[2] + red[3] + red[4] + red[5] + red[6] + red[7]) *
                 (1.0f / 768.0f);
    __syncthreads();
    float vs = 0.f;
#pragma unroll
    for (int r = 0; r < 3; r++) { float d = v[r] - mean; vs += d * d; }
#pragma unroll
    for (int o = 16; o; o >>= 1) vs += __shfl_xor_sync(0xffffffffu, vs, o);
    if (lane == 0) red[w] = vs;
    __syncthreads();
    float var = (red[0] + red[1] + red[2] + red[3] + red[4] + red[5] + red[6] + red[7]) *
                (1.0f / 768.0f);
    float rstd = rsqrtf(var + 1e-5f);
#pragma unroll
    for (int r = 0; r < 3; r++) {
        int e = tid + 256 * r;
        xn[b * Dd + e] = (v[r] - mean) * rstd * g[e] + bb[e];
    }
}

// ---------------- fused pre-step + LN1 (standalone, t=0 only) ----------------
__global__ void prestep_ln_k(float* __restrict__ x, const float* __restrict__ cp,
                             const float* __restrict__ w_pp, const float* __restrict__ b_pp,
                             const float* __restrict__ g_pp, const float* __restrict__ be_pp,
                             const float* __restrict__ te, const float* __restrict__ g1,
                             const float* __restrict__ b1_, float* __restrict__ xn) {
    int b = blockIdx.x, tid = threadIdx.x;
    __shared__ float red[8];
    int lane = tid & 31, w = tid >> 5;
    float c0 = cp[b * 2], c1 = cp[b * 2 + 1];
    float v[3];
    float s = 0.f;
#pragma unroll
    for (int r = 0; r < 3; r++) {
        int e = tid + 256 * r;
        v[r] = c0 * w_pp[e] + c1 * w_pp[Dd + e] + b_pp[e];
        s += v[r];
    }
#pragma unroll
    for (int o = 16; o; o >>= 1) s += __shfl_xor_sync(0xffffffffu, s, o);
    if (lane == 0) red[w] = s;
    __syncthreads();
    float mean = (red[0] + red[1] + red[2] + red[3] + red[4] + red[5] + red[6] + red[7]) *
                 (1.0f / 768.0f);
    __syncthreads();
    float vs = 0.f;
#pragma unroll
    for (int r = 0; r < 3; r++) { float d = v[r] - mean; vs += d * d; }
#pragma unroll
    for (int o = 16; o; o >>= 1) vs += __shfl_xor_sync(0xffffffffu, vs, o);
    if (lane == 0) red[w] = vs;
    __syncthreads();
    float var = (red[0] + red[1] + red[2] + red[3] + red[4] + red[5] + red[6] + red[7]) *
                (1.0f / 768.0f);
    float rstd = rsqrtf(var + 1e-5f);
    float xv[3];
    float s2 = 0.f;
#pragma unroll
    for (int r = 0; r < 3; r++) {
        int e = tid + 256 * r;
        float pq = (v[r] - mean) * rstd * g_pp[e] + be_pp[e];
        pq = fmaxf(pq, 0.f);
        xv[r] = x[b * Dd + e] + pq + te[e];
        x[b * Dd + e] = xv[r];
        s2 += xv[r];
    }
    __syncthreads();
#pragma unroll
    for (int o = 16; o; o >>= 1) s2 += __shfl_xor_sync(0xffffffffu, s2, o);
    if (lane == 0) red[w] = s2;
    __syncthreads();
    float mean2 = (red[0] + red[1] + red[2] + red[3] + red[4] + red[5] + red[6] + red[7]) *
                  (1.0f / 768.0f);
    __syncthreads();
    float vs2 = 0.f;
#pragma unroll
    for (int r = 0; r < 3; r++) { float d = xv[r] - mean2; vs2 += d * d; }
#pragma unroll
    for (int o = 16; o; o >>= 1) vs2 += __shfl_xor_sync(0xffffffffu, vs2, o);
    if (lane == 0) red[w] = vs2;
    __syncthreads();
    float var2 = (red[0] + red[1] + red[2] + red[3] + red[4] + red[5] + red[6] + red[7]) *
                 (1.0f / 768.0f);
    float rstd2 = rsqrtf(var2 + 1e-5f);
#pragma unroll
    for (int r = 0; r < 3; r++) {
        int e = tid + 256 * r;
        xn[b * Dd + e] = (xv[r] - mean2) * rstd2 * g1[e] + b1_[e];
    }
}

// ---------------- attention: 384 threads; 2 rows/warp scores; 8-seg AV -------
__global__ __launch_bounds__(384) void attn_k(const float* __restrict__ part,
                                              const float* __restrict__ bq,
                                              const __half* __restrict__ Kl,
                                              const __half* __restrict__ Vl,
                                              float* __restrict__ out) {
    const float SCALE = 0.1020620726159657f;  // 1/sqrt(96)
    int bh = blockIdx.x;
    int b = bh >> 3, h = bh & 7;
    const __half* Kp = Kl + (size_t)(b * Hh + h) * Nn_ * HDd;
    const __half* Vp = Vl + (size_t)(b * Hh + h) * Nn_ * HDd;
    int tid = threadIdx.x, lane = tid & 31, w = tid >> 5;
    __shared__ float qs[HDd];
    __shared__ float sa[Nn_];
    __shared__ float red[12];
    __shared__ float red2[12];
    __shared__ float2 vpart[8][48];
    if (tid < HDd) {
        int idx = b * Dd + h * HDd + tid;
        float qv = bq[h * HDd + tid];
#pragma unroll
        for (int r = 0; r < NSPLIT; r++) qv += part[r * XD_ELEMS + idx];
        qs[tid] = qv;
    }
    __syncthreads();
    {
        int sub = lane & 15;
        int rhalf = lane >> 4;
        float q0 = qs[sub * 6 + 0], q1 = qs[sub * 6 + 1], q2 = qs[sub * 6 + 2];
        float q3 = qs[sub * 6 + 3], q4 = qs[sub * 6 + 4], q5 = qs[sub * 6 + 5];
        for (int pr = w; pr < 128; pr += 12) {
            int n = 2 * pr + rhalf;
            const __half2* kr = (const __half2*)(Kp + (size_t)n * HDd);
            float2 k0 = __half22float2(kr[sub * 3 + 0]);
            float2 k1 = __half22float2(kr[sub * 3 + 1]);
            float2 k2 = __half22float2(kr[sub * 3 + 2]);
            float p = q0 * k0.x + q1 * k0.y + q2 * k1.x + q3 * k1.y + q4 * k2.x + q5 * k2.y;
#pragma unroll
            for (int o = 8; o; o >>= 1) p += __shfl_xor_sync(0xffffffffu, p, o);
            if (sub == 0) sa[n] = p * SCALE;
        }
    }
    __syncthreads();
    float m = (tid < Nn_) ? sa[tid] : -1e30f;
#pragma unroll
    for (int o = 16; o; o >>= 1) m = fmaxf(m, __shfl_xor_sync(0xffffffffu, m, o));
    if (lane == 0) red[w] = m;
    __syncthreads();
    m = red[0];
#pragma unroll
    for (int i = 1; i < 12; i++) m = fmaxf(m, red[i]);
    float e = 0.f;
    if (tid < Nn_) {
        e = expf(sa[tid] - m);
        sa[tid] = e;
    }
#pragma unroll
    for (int o = 16; o; o >>= 1) e += __shfl_xor_sync(0xffffffffu, e, o);
    if (lane == 0) red2[w] = e;
    __syncthreads();
    float tot = 0.f;
#pragma unroll
    for (int i = 0; i < 12; i++) tot += red2[i];
    float inv = 1.0f / tot;
    int seg = tid / 48, p_ = tid % 48;
    int ns = seg * 32;
    float2 acc = make_float2(0.f, 0.f);
#pragma unroll 8
    for (int n = ns; n < ns + 32; n++) {
        float2 vv = __half22float2(((const __half2*)(Vp + (size_t)n * HDd))[p_]);
        float sv = sa[n];
        acc.x += sv * vv.x;
        acc.y += sv * vv.y;
    }
    vpart[seg][p_] = acc;
    __syncthreads();
    if (tid < 48) {
        float2 r = make_float2(0.f, 0.f);
#pragma unroll
        for (int s2 = 0; s2 < 8; s2++) {
            float2 pv = vpart[s2][tid];
            r.x += pv.x;
            r.y += pv.y;
        }
        out[(size_t)b * Dd + h * HDd + 2 * tid] = r.x * inv;
        out[(size_t)b * Dd + h * HDd + 2 * tid + 1] = r.y * inv;
    }
}

// ---------------- fused decoder tail + next-step prestep ---------------------
__global__ __launch_bounds__(256) void dec2pre_k(
    const float* __restrict__ part, const float* __restrict__ bd1,
    const float* __restrict__ w2, const float* __restrict__ b2,
    float* __restrict__ cp, float* __restrict__ out, int t, int last,
    float* __restrict__ x, const float* __restrict__ w_pp, const float* __restrict__ b_pp,
    const float* __restrict__ g_pp, const float* __restrict__ be_pp,
    const float* __restrict__ te, const float* __restrict__ g1,
    const float* __restrict__ b1_, float* __restrict__ xn) {
    int b = blockIdx.x, tid = threadIdx.x;
    int lane = tid & 31, w = tid >> 5;
    __shared__ float red[8];
    __shared__ float r0s[8], r1s[8];
    __shared__ float cps[2];
    float a0 = 0.f, a1 = 0.f;
#pragma unroll
    for (int r = 0; r < 3; r++) {
        int e = tid + 256 * r;
        int idx = b * Dd + e;
        float s = bd1[e];
#pragma unroll
        for (int q = 0; q < NSPLIT; q++) s += part[q * XD_ELEMS + idx];
        float ge = gelu_exact(s);
        a0 += ge * w2[e * 2];
        a1 += ge * w2[e * 2 + 1];
    }
#pragma unroll
    for (int o = 16; o; o >>= 1) {
        a0 += __shfl_xor_sync(0xffffffffu, a0, o);
        a1 += __shfl_xor_sync(0xffffffffu, a1, o);
    }
    if (lane == 0) { r0s[w] = a0; r1s[w] = a1; }
    __syncthreads();
    if (tid == 0) {
        float d0 = b2[0], d1 = b2[1];
#pragma unroll
        for (int i = 0; i < 8; i++) { d0 += r0s[i]; d1 += r1s[i]; }
        float c0 = cp[b * 2] + d0, c1 = cp[b * 2 + 1] + d1;
        cp[b * 2] = c0;
        cp[b * 2 + 1] = c1;
        out[(size_t)(b * Tt + t) * 2 + 0] = c0;
        out[(size_t)(b * Tt + t) * 2 + 1] = c1;
        cps[0] = c0;
        cps[1] = c1;
    }
    if (last) return;
    __syncthreads();
    float c0 = cps[0], c1 = cps[1];
    float v[3];
    float s = 0.f;
#pragma unroll
    for (int r = 0; r < 3; r++) {
        int e = tid + 256 * r;
        v[r] = c0 * w_pp[e] + c1 * w_pp[Dd + e] + b_pp[e];
        s += v[r];
    }
#pragma unroll
    for (int o = 16; o; o >>= 1) s += __shfl_xor_sync(0xffffffffu, s, o);
    if (lane == 0) red[w] = s;
    __syncthreads();
    float mean = (red[0] + red[1] + red[2] + red[3] + red[4] + red[5] + red[6] + red[7]) *
                 (1.0f / 768.0f);
    __syncthreads();
    float vs = 0.f;
#pragma unroll
    for (int r = 0; r < 3; r++) { float d = v[r] - mean; vs += d * d; }
#pragma unroll
    for (int o = 16; o; o >>= 1) vs += __shfl_xor_sync(0xffffffffu, vs, o);
    if (lane == 0) red[w] = vs;
    __syncthreads();
    float var = (red[0] + red[1] + red[2] + red[3] + red[4] + red[5] + red[6] + red[7]) *
                (1.0f / 768.0f);
    float rstd = rsqrtf(var + 1e-5f);
    float xv[3];
    float s2 = 0.f;
#pragma unroll
    for (int r = 0; r < 3; r++) {
        int e = tid + 256 * r;
        float pq = (v[r] - mean) * rstd * g_pp[e] + be_pp[e];
        pq = fmaxf(pq, 0.f);
        xv[r] = x[b * Dd + e] + pq + te[e];
        x[b * Dd + e] = xv[r];
        s2 += xv[r];
    }
    __syncthreads();
#pragma unroll
    for (int o = 16; o; o >>= 1) s2 += __shfl_xor_sync(0xffffffffu, s2, o);
    if (lane == 0) red[w] = s2;
    __syncthreads();
    float mean2 = (red[0] + red[1] + red[2] + red[3] + red[4] + red[5] + red[6] + red[7]) *
                  (1.0f / 768.0f);
    __syncthreads();
    float vs2 = 0.f;
#pragma unroll
    for (int r = 0; r < 3; r++) { float d = xv[r] - mean2; vs2 += d * d; }
#pragma unroll
    for (int o = 16; o; o >>= 1) vs2 += __shfl_xor_sync(0xffffffffu, vs2, o);
    if (lane == 0) red[w] = vs2;
    __syncthreads();
    float var2 = (red[0] + red[1] + red[2] + red[3] + red[4] + red[5] + red[6] + red[7]) *
                 (1.0f / 768.0f);
    float rstd2 = rsqrtf(var2 + 1e-5f);
#pragma unroll
    for (int r = 0; r < 3; r++) {
        int e = tid + 256 * r;
        xn[b * Dd + e] = (xv[r] - mean2) * rstd2 * g1[e] + b1_[e];
    }
}

// ---------------- host orchestration -----------------------------------------
extern "C" void kernel_launch(void* const* d_in, const int* in_sizes, int n_in,
                              void* d_out, int out_size) {
    const float* feats   = (const float*)d_in[0];
    const float* past    = (const float*)d_in[1];
    const float* w_qinit = (const float*)d_in[2];
    const float* b_qinit = (const float*)d_in[3];
    const float* pos_enc = (const float*)d_in[4];
    const float* w_pp    = (const float*)d_in[5];
    const float* b_pp    = (const float*)d_in[6];
    const float* g_pp    = (const float*)d_in[7];
    const float* be_pp   = (const float*)d_in[8];
    const float* time_emb= (const float*)d_in[9];
    const float* Wq      = (const float*)d_in[10];
    const float* bq      = (const float*)d_in[11];
    const float* Wk      = (const float*)d_in[12];
    const float* bk      = (const float*)d_in[13];
    const float* Wv      = (const float*)d_in[14];
    const float* bv      = (const float*)d_in[15];
    const float* Wo      = (const float*)d_in[16];
    const float* bo      = (const float*)d_in[17];
    const float* ln1_g   = (const float*)d_in[18];
    const float* ln1_b   = (const float*)d_in[19];
    const float* W1      = (const float*)d_in[20];
    const float* b1      = (const float*)d_in[21];
    const float* W2      = (const float*)d_in[22];
    const float* b2      = (const float*)d_in[23];
    const float* ln2_g   = (const float*)d_in[24];
    const float* ln2_b   = (const float*)d_in[25];
    const float* w_dec1  = (const float*)d_in[26];
    const float* b_dec1  = (const float*)d_in[27];
    const float* w_dec2  = (const float*)d_in[28];
    const float* b_dec2  = (const float*)d_in[29];
    const int*   intent  = (const int*)d_in[30];
    float* out = (float*)d_out;

    float *x, *xn, *att, *part, *part2, *cp;
    __half *tokh, *Wth, *Wsp, *Kb, *Vb;
    cudaGetSymbolAddress((void**)&tokh,  g_tokh);
    cudaGetSymbolAddress((void**)&Wth,   g_Wth);
    cudaGetSymbolAddress((void**)&Wsp,   g_Wsp);
    cudaGetSymbolAddress((void**)&Kb,    g_K);
    cudaGetSymbolAddress((void**)&Vb,    g_V);
    cudaGetSymbolAddress((void**)&x,     g_x);
    cudaGetSymbolAddress((void**)&xn,    g_xn);
    cudaGetSymbolAddress((void**)&att,   g_attn);
    cudaGetSymbolAddress((void**)&part,  g_part);
    cudaGetSymbolAddress((void**)&part2, g_part2);
    cudaGetSymbolAddress((void**)&cp,    g_cp);

    const int SMH  = 3 * (128 * 40 + 128 * 40) * 2;  // 61440 B, ring-3
    const int SMSK = 61440;                          // hi/lo double-buffer
    cudaFuncSetAttribute(hgemm_kv_k, cudaFuncAttributeMaxDynamicSharedMemorySize, SMH);
    cudaFuncSetAttribute(hgemm_sk<0>, cudaFuncAttributeMaxDynamicSharedMemorySize, SMSK);
    cudaFuncSetAttribute(hgemm_sk<1>, cudaFuncAttributeMaxDynamicSharedMemorySize, SMSK);

    // Phase 1: prep + KV projections (packed single launch, grid.z = 4)
    tokens_k<<<dim3(Nn_ / 32, Dd / 32, Bn), dim3(32, 8)>>>(feats, pos_enc, tokh);
    wtrans_k<<<dim3(Dd / 32, Dd / 32, 4), dim3(32, 8)>>>(Wk, Wv, Wth);
    for (int l = 0; l < Ll; l++) {
        wsplit_k<<<dim3(24, 24), dim3(32, 8)>>>(Wq + (size_t)l * Dd * Dd,
                                                Wsp + WSP_Q + (size_t)l * 2 * Dd * Dd, Dd, Dd);
        wsplit_k<<<dim3(24, 24), dim3(32, 8)>>>(Wo + (size_t)l * Dd * Dd,
                                                Wsp + WSP_O + (size_t)l * 2 * Dd * Dd, Dd, Dd);
        wsplit_k<<<dim3(24, 96), dim3(32, 8)>>>(W1 + (size_t)l * Dd * DFf,
                                                Wsp + WSP_W1 + (size_t)l * 2 * Dd * DFf, Dd, DFf);
        wsplit_k<<<dim3(96, 24), dim3(32, 8)>>>(W2 + (size_t)l * DFf * Dd,
                                                Wsp + WSP_W2 + (size_t)l * 2 * Dd * DFf, DFf, Dd);
    }
    wsplit_k<<<dim3(24, 24), dim3(32, 8)>>>(w_dec1, Wsp + WSP_D1, Dd, Dd);
    context_k<<<Bn, 256>>>(past, w_qinit, b_qinit, intent, x, cp);
    hgemm_kv_k<<<dim3(6, 512, 4), 256, SMH>>>(tokh, Wth, bk, bv, Kb, Vb, Dd);

    // Phase 2: sequential scan
    prestep_ln_k<<<Bn, 256>>>(x, cp, w_pp, b_pp, g_pp, be_pp,
                              time_emb, ln1_g, ln1_b, xn);
    for (int t = 0; t < Tt; t++) {
        for (int l = 0; l < Ll; l++) {
            // q partials = LN1(x) @ Wq
            hgemm_sk<0><<<dim3(6, 4, 8), 128, SMSK>>>(
                xn, nullptr, nullptr, nullptr,
                Wsp + WSP_Q + (size_t)l * 2 * Dd * Dd, part, Bn, Dd, Dd, Dd / 8);
            attn_k<<<Bn * Hh, 384>>>(part, bq + l * Dd, Kb + (size_t)l * KV_LOFF,
                                     Vb + (size_t)l * KV_LOFF, att);
            // o partials = attn @ Wo ; x += o + bo ; xn = LN2(x)
            hgemm_sk<0><<<dim3(6, 4, 8), 128, SMSK>>>(
                att, nullptr, nullptr, nullptr,
                Wsp + WSP_O + (size_t)l * 2 * Dd * Dd, part, Bn, Dd, Dd, Dd / 8);
            reduce_res_ln_k<<<Bn, 256>>>(part, bo + l * Dd, x, ln2_g + l * Dd,
                                         ln2_b + l * Dd, xn);
            // FFN1 partials = xn @ W1 (split-K 2; gelu+bias folded into FFN2 stage)
            hgemm_sk<0><<<dim3(24, 4, 2), 128, SMSK>>>(
                xn, nullptr, nullptr, nullptr,
                Wsp + WSP_W1 + (size_t)l * 2 * Dd * DFf, part, Bn, Dd, DFf, Dd / 2);
            // FFN2 partials = gelu(b1 + P0 + P1) @ W2  (split-K 8)
            hgemm_sk<1><<<dim3(6, 4, 8), 128, SMSK>>>(
                nullptr, part, part + H1_ELEMS, b1 + (size_t)l * DFf,
                Wsp + WSP_W2 + (size_t)l * 2 * Dd * DFf, part2, Bn, DFf, Dd, DFf / 8);
            if (l == 0)
                reduce_res_ln_k<<<Bn, 256>>>(part2, b2 + l * Dd, x, ln1_g + Dd,
                                             ln1_b + Dd, xn);
            else
                reduce8res_k<<<XD_ELEMS / 1024, 256>>>(part2, b2 + l * Dd, x);
        }
        // decoder + fused next-step prestep
        hgemm_sk<0><<<dim3(6, 4, 8), 128, SMSK>>>(
            x, nullptr, nullptr, nullptr, Wsp + WSP_D1, part, Bn, Dd, Dd, Dd / 8);
        int last = (t == Tt - 1);
        const float* te_next = time_emb + (size_t)(last ? t : t + 1) * Dd;
        dec2pre_k<<<Bn, 256>>>(part, b_dec1, w_dec2, b_dec2, cp, out, t, last,
                               x, w_pp, b_pp, g_pp, be_pp, te_next, ln1_g, ln1_b, xn);
    }
}